// round 1
// baseline (speedup 1.0000x reference)
#include <cuda_runtime.h>

#define BB 2
#define CC 32
#define DD 64
#define HH 128
#define WW 128
#define NBC (BB*CC)

// Scratch accumulators (allocation-free: device globals)
__device__ double g_crown[NBC];
__device__ double g_root[NBC];
__device__ double g_tv[3];   // sx, sy, sz

__global__ void init_kernel() {
    int i = threadIdx.x;
    if (i < NBC) { g_crown[i] = 0.0; g_root[i] = 0.0; }
    if (i < 3)   g_tv[i] = 0.0;
}

// One CTA per z-slice (blockIdx.x = b*CC*DD + c*DD + d), 256 threads = 8 warps.
// Warp w handles rows h = w, w+8, ..., 120+w. Lane = float4 column index (32 per row).
__global__ __launch_bounds__(256) void slice_kernel(const float* __restrict__ seg) {
    const int s  = blockIdx.x;
    const int d  = s % DD;
    const int bc = s / DD;

    const float* slice = seg + (size_t)s * (HH * WW);
    const float* nextslice = slice + (HH * WW);   // only read if d < DD-1

    const int warp = threadIdx.x >> 5;
    const int lane = threadIdx.x & 31;
    const bool has_z = (d < DD - 1);

    float ssum = 0.f, sx = 0.f, sy = 0.f, sz = 0.f;

    #pragma unroll
    for (int h = warp; h < HH; h += 8) {
        const float4 cur = reinterpret_cast<const float4*>(slice + h * WW)[lane];

        ssum += (cur.x + cur.y) + (cur.z + cur.w);

        // x diffs: 3 intra-float4 + 1 across lanes via shuffle
        float nx = __shfl_down_sync(0xffffffffu, cur.x, 1);
        sx += fabsf(cur.y - cur.x) + fabsf(cur.z - cur.y) + fabsf(cur.w - cur.z);
        if (lane < 31) sx += fabsf(nx - cur.w);

        // y diff: row h+1 in same slice (L1-resident; also read as cur by another warp)
        if (h < HH - 1) {
            const float4 yn = reinterpret_cast<const float4*>(slice + (h + 1) * WW)[lane];
            sy += fabsf(yn.x - cur.x) + fabsf(yn.y - cur.y)
                + fabsf(yn.z - cur.z) + fabsf(yn.w - cur.w);
        }

        // z diff: same (h,w) in slice d+1 (adjacent CTA's slice -> L2-resident)
        if (has_z) {
            const float4 zn = reinterpret_cast<const float4*>(nextslice + h * WW)[lane];
            sz += fabsf(zn.x - cur.x) + fabsf(zn.y - cur.y)
                + fabsf(zn.z - cur.z) + fabsf(zn.w - cur.w);
        }
    }

    // warp reduce all 4 quantities
    #pragma unroll
    for (int off = 16; off > 0; off >>= 1) {
        ssum += __shfl_xor_sync(0xffffffffu, ssum, off);
        sx   += __shfl_xor_sync(0xffffffffu, sx,   off);
        sy   += __shfl_xor_sync(0xffffffffu, sy,   off);
        sz   += __shfl_xor_sync(0xffffffffu, sz,   off);
    }

    __shared__ float sh[4][8];
    if (lane == 0) {
        sh[0][warp] = ssum; sh[1][warp] = sx; sh[2][warp] = sy; sh[3][warp] = sz;
    }
    __syncthreads();

    if (threadIdx.x == 0) {
        double tsum = 0.0, tx = 0.0, ty = 0.0, tz = 0.0;
        #pragma unroll
        for (int w = 0; w < 8; w++) {
            tsum += (double)sh[0][w];
            tx   += (double)sh[1][w];
            ty   += (double)sh[2][w];
            tz   += (double)sh[3][w];
        }
        if (d < DD / 2) atomicAdd(&g_crown[bc], tsum);
        else            atomicAdd(&g_root[bc],  tsum);
        atomicAdd(&g_tv[0], tx);
        atomicAdd(&g_tv[1], ty);
        atomicAdd(&g_tv[2], tz);
    }
}

__global__ void finalize_kernel(float* __restrict__ out) {
    __shared__ double sh[NBC];
    const int i = threadIdx.x;   // 64 threads

    double crown = g_crown[i];
    double root  = g_root[i];
    double total = crown + root;
    double loss = 0.0;
    if (total > 0.0 && root > 0.0) {
        double r = crown / root - 1.2;
        loss = r * r;
    }
    sh[i] = loss;
    __syncthreads();

    #pragma unroll
    for (int off = 32; off > 0; off >>= 1) {
        if (i < off) sh[i] += sh[i + off];
        __syncthreads();
    }

    if (i == 0) {
        double cr_loss = sh[0] / (double)NBC;
        double Nx = (double)BB * CC * DD * HH * (WW - 1);
        double Ny = (double)BB * CC * DD * (HH - 1) * WW;
        double Nz = (double)BB * CC * (DD - 1) * HH * WW;
        double tv = g_tv[0] / Nx + g_tv[1] / Ny + g_tv[2] / Nz;

        double crown_root = cr_loss * 2.0;   // CROWN_ROOT_W
        double smooth     = tv * 1.5;        // SMOOTH_W
        out[0] = (float)crown_root;
        out[1] = (float)smooth;
        out[2] = (float)(crown_root + smooth);
    }
}

extern "C" void kernel_launch(void* const* d_in, const int* in_sizes, int n_in,
                              void* d_out, int out_size) {
    const float* seg = (const float*)d_in[0];
    float* out = (float*)d_out;

    init_kernel<<<1, 128>>>();
    slice_kernel<<<BB * CC * DD, 256>>>(seg);
    finalize_kernel<<<1, NBC>>>(out);
}